// round 15
// baseline (speedup 1.0000x reference)
#include <cuda_runtime.h>
#include <cuda_fp16.h>
#include <math.h>
#include <stdint.h>

#define BMAX 65536
#define BN_EPS 1e-5f
#define PAD 136   // halves per tile row: 272B = 17*16B -> ldmatrix conflict-free

// ---------------- scratch (static device globals; zero-initialized at load) ---
static __device__ float  g_q[BMAX * 4];
static __device__ __half g_h2h[(size_t)BMAX * 256];    // 32 MB, L2-resident
static __device__ __half g_w2h[256 * 128];
static __device__ __half g_w3h[256 * 256];
static __device__ float g_stat1[8 * 20];    // k_sim sumz/sumzz partials (8-way spread)
                                            // zeroed at end of k_fc3 for next run
static __device__ float g_s2s[4 * 256];     // fc2 column-sum partials (4-way spread)
static __device__ float g_s2q[4 * 256];     // zeroed in k_sim (fc2 runs after)

// ---------------- PTX helpers --------------------------------------------------
__device__ __forceinline__ uint32_t smem_u32(const void* p) {
    uint32_t a;
    asm("{ .reg .u64 t; cvta.to.shared.u64 t, %1; cvt.u32.u64 %0, t; }" : "=r"(a) : "l"(p));
    return a;
}
__device__ __forceinline__ void ldmx4(uint32_t& d0, uint32_t& d1, uint32_t& d2, uint32_t& d3,
                                      uint32_t addr) {
    asm volatile("ldmatrix.sync.aligned.m8n8.x4.shared.b16 {%0,%1,%2,%3}, [%4];"
                 : "=r"(d0), "=r"(d1), "=r"(d2), "=r"(d3) : "r"(addr));
}
__device__ __forceinline__ void mma_f16(float* c, const uint32_t* a, const uint32_t* b) {
    asm volatile(
        "mma.sync.aligned.m16n8k16.row.col.f32.f16.f16.f32 "
        "{%0,%1,%2,%3}, {%4,%5,%6,%7}, {%8,%9}, {%0,%1,%2,%3};"
        : "+f"(c[0]), "+f"(c[1]), "+f"(c[2]), "+f"(c[3])
        : "r"(a[0]), "r"(a[1]), "r"(a[2]), "r"(a[3]), "r"(b[0]), "r"(b[1]));
}
__device__ __forceinline__ uint32_t pack_half2(float x, float y) {
    __half2 h = __floats2half2_rn(x, y);
    return *(uint32_t*)&h;
}
__device__ __forceinline__ float tanh_fast(float x) {
    float y;
    asm("tanh.approx.f32 %0, %1;" : "=f"(y) : "f"(x));
    return y;
}
__device__ __forceinline__ void cp_async16(uint32_t saddr, const void* gptr) {
    asm volatile("cp.async.ca.shared.global [%0], [%1], 16;" :: "r"(saddr), "l"(gptr));
}
#define CP_COMMIT() asm volatile("cp.async.commit_group;" ::: "memory")
#define CP_WAIT0()  asm volatile("cp.async.wait_group 0;" ::: "memory")

// ---------------- quantum simulator (4 sincos/thread) + stats + fused prep ----
__global__ void k_sim(const float* __restrict__ x, const float* __restrict__ qp,
                      const float* __restrict__ w2, const float* __restrict__ w3,
                      int Bc) {
    int t = blockIdx.x * blockDim.x + threadIdx.x;

    if (t < 32768) g_w2h[t] = __float2half_rn(w2[t]);
    if (t < 65536) g_w3h[t] = __float2half_rn(w3[t]);
    if (t < 1024) { g_s2s[t] = 0.f; g_s2q[t] = 0.f; }

    __shared__ float sqp[24], cqp[24];
    __shared__ float phT[3][16], phTi[3][16];
    if (threadIdx.x < 24) {
        float s, c;
        __sincosf(0.5f * qp[threadIdx.x], &s, &c);
        sqp[threadIdx.x] = s; cqp[threadIdx.x] = c;
    }
    __syncthreads();
    if (threadIdx.x < 48) {
        int d = threadIdx.x >> 4, idx = threadIdx.x & 15;
        float pr = 1.f, pi = 0.f;
        #pragma unroll
        for (int i = 0; i < 4; i++) {
            int m = 1 << (3 - i);
            float c = cqp[d * 8 + 4 + i];
            float s = (idx & m) ? sqp[d * 8 + 4 + i] : -sqp[d * 8 + 4 + i];
            float nr = pr * c - pi * s;
            float ni = pr * s + pi * c;
            pr = nr; pi = ni;
        }
        phT[d][idx] = pr; phTi[d][idx] = pi;
    }
    __syncthreads();

    float z[4] = {0.f, 0.f, 0.f, 0.f};
    if (t < Bc) {
        float sx[4], cx[4];
        #pragma unroll
        for (int i = 0; i < 4; i++) {
            float xi = x[t * 4 + i];
            __sincosf(0.5f * xi, &sx[i], &cx[i]);
        }

        float re[16], im[16];
        {
            float sy[4], cy[4];
            #pragma unroll
            for (int i = 0; i < 4; i++) {
                float sq = sqp[i], cq = cqp[i];
                sy[i] = sx[i] * cq + cx[i] * sq;
                cy[i] = cx[i] * cq - sx[i] * sq;
            }
            float p01[4] = {cy[0]*cy[1], cy[0]*sy[1], sy[0]*cy[1], sy[0]*sy[1]};
            float p23[4] = {cy[2]*cy[3], cy[2]*sy[3], sy[2]*cy[3], sy[2]*sy[3]};
            float r[16];
            #pragma unroll
            for (int idx = 0; idx < 16; idx++)
                r[idx] = p01[idx >> 2] * p23[idx & 3];
            #pragma unroll
            for (int i = 0; i < 4; i++) {
                int cm = 1 << (3 - i);
                int tm = 1 << (3 - ((i + 1) & 3));
                #pragma unroll
                for (int idx = 0; idx < 16; idx++) {
                    if ((idx & cm) && !(idx & tm)) {
                        int p = idx | tm;
                        float tr = r[idx]; r[idx] = r[p]; r[p] = tr;
                    }
                }
            }
            #pragma unroll
            for (int idx = 0; idx < 16; idx++) {
                re[idx] = r[idx] * phT[0][idx];
                im[idx] = r[idx] * phTi[0][idx];
            }
        }

        #pragma unroll
        for (int d = 1; d < 3; d++) {
            #pragma unroll
            for (int i = 0; i < 4; i++) {
                float sq = sqp[d * 8 + i], cq = cqp[d * 8 + i];
                float s = sx[i] * cq + cx[i] * sq;
                float c = cx[i] * cq - sx[i] * sq;
                int m = 1 << (3 - i);
                #pragma unroll
                for (int idx = 0; idx < 16; idx++) {
                    if ((idx & m) == 0) {
                        int p = idx | m;
                        float a0r = re[idx], a0i = im[idx];
                        float a1r = re[p],  a1i = im[p];
                        re[idx] = c * a0r - s * a1r;  im[idx] = c * a0i - s * a1i;
                        re[p]   = s * a0r + c * a1r;  im[p]   = s * a0i + c * a1i;
                    }
                }
            }
            #pragma unroll
            for (int i = 0; i < 4; i++) {
                int cm = 1 << (3 - i);
                int tm = 1 << (3 - ((i + 1) & 3));
                #pragma unroll
                for (int idx = 0; idx < 16; idx++) {
                    if ((idx & cm) && !(idx & tm)) {
                        int p = idx | tm;
                        float tr = re[idx]; re[idx] = re[p]; re[p] = tr;
                        float ti = im[idx]; im[idx] = im[p]; im[p] = ti;
                    }
                }
            }
            #pragma unroll
            for (int idx = 0; idx < 16; idx++) {
                float phr = phT[d][idx], phi = phTi[d][idx];
                float r0 = re[idx], i0 = im[idx];
                re[idx] = r0 * phr - i0 * phi;
                im[idx] = r0 * phi + i0 * phr;
            }
        }

        float pr[16];
        #pragma unroll
        for (int idx = 0; idx < 16; idx++)
            pr[idx] = re[idx] * re[idx] + im[idx] * im[idx];
        #pragma unroll
        for (int i = 0; i < 4; i++) {
            int m = 1 << (3 - i);
            float acc = 0.f;
            #pragma unroll
            for (int idx = 0; idx < 16; idx++)
                acc += (idx & m) ? -pr[idx] : pr[idx];
            z[i] = acc;
        }
        *(float4*)(g_q + (size_t)t * 4) = make_float4(z[0], z[1], z[2], z[3]);
    }

    __shared__ float wred[4][20];
    float vals[20];
    #pragma unroll
    for (int a = 0; a < 4; a++) vals[a] = z[a];
    #pragma unroll
    for (int a = 0; a < 4; a++)
        #pragma unroll
        for (int b = 0; b < 4; b++) vals[4 + a * 4 + b] = z[a] * z[b];
    #pragma unroll
    for (int v = 0; v < 20; v++) {
        #pragma unroll
        for (int off = 16; off > 0; off >>= 1)
            vals[v] += __shfl_xor_sync(0xffffffffu, vals[v], off);
    }
    int lane = threadIdx.x & 31, warp = threadIdx.x >> 5;
    if (lane == 0) {
        #pragma unroll
        for (int v = 0; v < 20; v++) wred[warp][v] = vals[v];
    }
    __syncthreads();
    if (threadIdx.x < 20) {
        float s = wred[0][threadIdx.x] + wred[1][threadIdx.x]
                + wred[2][threadIdx.x] + wred[3][threadIdx.x];
        atomicAdd(&g_stat1[(blockIdx.x & 7) * 20 + threadIdx.x], s);
    }
}

// ---------------- fc2: fp16 mma, cp.async B, fused bn1 + bn2 stats ------------
__global__ void __launch_bounds__(256, 2)
k_fc2(const float* __restrict__ w1,
      const float* __restrict__ bn1g, const float* __restrict__ bn1b,
      int Bc, float binv) {
    extern __shared__ char dynsm[];
    __half* As = (__half*)dynsm;             // [128][PAD]
    __half* Bs = As + 128 * PAD;             // [128][PAD]
    __shared__ float qs[512], w1s[512], sc1s[128], sh1s[128];
    __shared__ float redS[8 * 32], redQ[8 * 32];
    __shared__ float st1[20];

    int tid = threadIdx.x;
    int row0 = blockIdx.x * 128;
    int bc = blockIdx.y;

    #pragma unroll
    for (int i = 0; i < 8; i++) {
        int idx = tid + i * 256;
        int n = idx >> 4, t = idx & 15;
        cp_async16(smem_u32(Bs + n * PAD + t * 8),
                   g_w2h + (size_t)(bc * 128 + n) * 128 + t * 8);
    }
    CP_COMMIT();

    if (tid < 20) {
        float s = 0.f;
        #pragma unroll
        for (int p = 0; p < 8; p++) s += g_stat1[p * 20 + tid];
        st1[tid] = s;
    }
    w1s[tid] = w1[tid];
    w1s[tid + 256] = w1[tid + 256];
    if (tid < 128) {
        int r = row0 + tid;
        float4 q = (r < Bc) ? *(const float4*)(g_q + (size_t)r * 4)
                            : make_float4(0.f, 0.f, 0.f, 0.f);
        *(float4*)(qs + tid * 4) = q;
    }
    __syncthreads();

    if (tid < 128) {
        int j = tid;
        float mu[4], C[16];
        #pragma unroll
        for (int a = 0; a < 4; a++) mu[a] = st1[a] * binv;
        #pragma unroll
        for (int a = 0; a < 4; a++)
            #pragma unroll
            for (int c = 0; c < 4; c++)
                C[a * 4 + c] = st1[4 + a * 4 + c] * binv - mu[a] * mu[c];
        float w[4];
        #pragma unroll
        for (int a = 0; a < 4; a++) w[a] = w1s[j * 4 + a];
        float m0v = 0.f, v = 0.f;
        #pragma unroll
        for (int a = 0; a < 4; a++) {
            m0v += w[a] * mu[a];
            #pragma unroll
            for (int c = 0; c < 4; c++) v += w[a] * w[c] * C[a * 4 + c];
        }
        float sc = bn1g[j] * rsqrtf(v + BN_EPS);
        sc1s[j] = sc;
        sh1s[j] = bn1b[j] - sc * m0v;
    }
    __syncthreads();

    #pragma unroll
    for (int i = 0; i < 8; i++) {
        int idx = tid + i * 256;
        int r = idx >> 4, g8 = (idx & 15) << 3;
        bool valid = (row0 + r < Bc);
        float4 qv = *(const float4*)(qs + r * 4);
        uint32_t pk[4];
        #pragma unroll
        for (int p = 0; p < 4; p++) {
            int f0 = g8 + 2 * p, f1 = f0 + 1;
            float d0 = qv.x * w1s[f0 * 4] + qv.y * w1s[f0 * 4 + 1]
                     + qv.z * w1s[f0 * 4 + 2] + qv.w * w1s[f0 * 4 + 3];
            float d1 = qv.x * w1s[f1 * 4] + qv.y * w1s[f1 * 4 + 1]
                     + qv.z * w1s[f1 * 4 + 2] + qv.w * w1s[f1 * 4 + 3];
            float v0 = valid ? fmaxf(fmaf(sc1s[f0], d0, sh1s[f0]), 0.f) : 0.f;
            float v1 = valid ? fmaxf(fmaf(sc1s[f1], d1, sh1s[f1]), 0.f) : 0.f;
            pk[p] = pack_half2(v0, v1);
        }
        *(uint4*)(As + r * PAD + g8) = make_uint4(pk[0], pk[1], pk[2], pk[3]);
    }
    CP_WAIT0();
    __syncthreads();

    int lane = tid & 31, wid = tid >> 5;
    int wr = wid >> 2, wc = wid & 3;
    int m0 = wr * 64, n0 = wc * 32;
    int lrow = lane & 7, mat = lane >> 3;
    int rb = (mat & 1) * 8, kb = (mat >> 1) * 8;

    uint32_t aA[4], bA[2];
    #pragma unroll
    for (int i = 0; i < 4; i++)
        aA[i] = smem_u32(As + (m0 + i * 16 + rb + lrow) * PAD + kb);
    #pragma unroll
    for (int j = 0; j < 2; j++)
        bA[j] = smem_u32(Bs + (n0 + j * 16 + rb + lrow) * PAD + kb);

    float acc[4][4][4];
    #pragma unroll
    for (int i = 0; i < 4; i++)
        #pragma unroll
        for (int j = 0; j < 4; j++)
            #pragma unroll
            for (int p = 0; p < 4; p++) acc[i][j][p] = 0.f;

    uint32_t afr[2][4][4], bfr[2][4][2];
    {
        #pragma unroll
        for (int i = 0; i < 4; i++)
            ldmx4(afr[0][i][0], afr[0][i][1], afr[0][i][2], afr[0][i][3], aA[i]);
        #pragma unroll
        for (int j2 = 0; j2 < 2; j2++)
            ldmx4(bfr[0][2*j2][0], bfr[0][2*j2+1][0], bfr[0][2*j2][1], bfr[0][2*j2+1][1], bA[j2]);
    }
    #pragma unroll
    for (int s = 0; s < 8; s++) {
        int cur = s & 1, nxt = cur ^ 1;
        if (s < 7) {
            #pragma unroll
            for (int i = 0; i < 4; i++)
                ldmx4(afr[nxt][i][0], afr[nxt][i][1], afr[nxt][i][2], afr[nxt][i][3],
                      aA[i] + (s + 1) * 32);
            #pragma unroll
            for (int j2 = 0; j2 < 2; j2++)
                ldmx4(bfr[nxt][2*j2][0], bfr[nxt][2*j2+1][0], bfr[nxt][2*j2][1],
                      bfr[nxt][2*j2+1][1], bA[j2] + (s + 1) * 32);
        }
        #pragma unroll
        for (int i = 0; i < 4; i++)
            #pragma unroll
            for (int j = 0; j < 4; j++)
                mma_f16(acc[i][j], afr[cur][i], bfr[cur][j]);
    }

    __syncthreads();
    __half* stage = As;
    float cs[4][2], cq[4][2];
    #pragma unroll
    for (int j = 0; j < 4; j++) { cs[j][0] = cs[j][1] = cq[j][0] = cq[j][1] = 0.f; }

    #pragma unroll
    for (int i = 0; i < 4; i++) {
        #pragma unroll
        for (int half = 0; half < 2; half++) {
            int rloc = m0 + i * 16 + (lane >> 2) + half * 8;
            #pragma unroll
            for (int j = 0; j < 4; j++) {
                float v0 = acc[i][j][half * 2 + 0];
                float v1 = acc[i][j][half * 2 + 1];
                int cloc = n0 + j * 8 + (lane & 3) * 2;
                *(uint32_t*)(stage + rloc * PAD + cloc) = pack_half2(v0, v1);
                cs[j][0] += v0; cs[j][1] += v1;
                cq[j][0] += v0 * v0; cq[j][1] += v1 * v1;
            }
        }
    }
    #pragma unroll
    for (int j = 0; j < 4; j++)
        #pragma unroll
        for (int p = 0; p < 2; p++) {
            #pragma unroll
            for (int off = 4; off < 32; off <<= 1) {
                cs[j][p] += __shfl_xor_sync(0xffffffffu, cs[j][p], off);
                cq[j][p] += __shfl_xor_sync(0xffffffffu, cq[j][p], off);
            }
        }
    if (lane < 4) {
        #pragma unroll
        for (int j = 0; j < 4; j++)
            #pragma unroll
            for (int p = 0; p < 2; p++) {
                int c32 = j * 8 + lane * 2 + p;
                redS[wid * 32 + c32] = cs[j][p];
                redQ[wid * 32 + c32] = cq[j][p];
            }
    }
    __syncthreads();

    #pragma unroll
    for (int i = 0; i < 8; i++) {
        int idx = tid + i * 256;
        int r = idx >> 4, t = idx & 15;
        if (row0 + r < Bc) {
            uint4 v = *(uint4*)(stage + r * PAD + t * 8);
            *(uint4*)(g_h2h + (size_t)(row0 + r) * 256 + bc * 128 + t * 8) = v;
        }
    }
    if (tid < 128) {
        int wcq = tid >> 5, c32 = tid & 31;
        float s = redS[wcq * 32 + c32] + redS[(4 + wcq) * 32 + c32];
        float q = redQ[wcq * 32 + c32] + redQ[(4 + wcq) * 32 + c32];
        int slot = (blockIdx.x & 3) * 256 + bc * 128 + tid;
        atomicAdd(&g_s2s[slot], s);
        atomicAdd(&g_s2q[slot], q);
    }
}

// ---------------- fc3: bc-merged — A transformed once, 4 mainloops ------------
__global__ void __launch_bounds__(256, 2)
k_fc3(const float* __restrict__ b3,
      const float* __restrict__ bn2g, const float* __restrict__ bn2b,
      float* __restrict__ out, int Bc, float binv) {
    extern __shared__ char dynsm[];
    __half* As0 = (__half*)dynsm;            // [128][PAD]  h2r cols 0..127
    __half* As1 = As0 + 128 * PAD;           // [128][PAD]  h2r cols 128..255
    __half* Bs  = As1 + 128 * PAD;           // [128][PAD]  reloaded per (bc,ck)
    __shared__ __half2 sc2h[128], sh2h[128];
    __shared__ float b3s[256];

    int tid = threadIdx.x;
    int row0 = blockIdx.x * 128;

    // B(bc=0, ck=0) issued immediately; flight overlaps params + A-transform
    #pragma unroll
    for (int i = 0; i < 8; i++) {
        int idx = tid + i * 256;
        int n = idx >> 4, t = idx & 15;
        cp_async16(smem_u32(Bs + n * PAD + t * 8),
                   g_w3h + (size_t)n * 256 + t * 8);
    }
    CP_COMMIT();

    // bn2 params for ALL 256 cols (once per block, was twice)
    if (tid < 128) {
        int j0 = 2 * tid, j1 = 2 * tid + 1;
        float s0g = 0.f, s1g = 0.f, q0g = 0.f, q1g = 0.f;
        #pragma unroll
        for (int p = 0; p < 4; p++) {
            s0g += g_s2s[p * 256 + j0];  s1g += g_s2s[p * 256 + j1];
            q0g += g_s2q[p * 256 + j0];  q1g += g_s2q[p * 256 + j1];
        }
        float m0v = s0g * binv, m1v = s1g * binv;
        float v0 = q0g * binv - m0v * m0v;
        float v1 = q1g * binv - m1v * m1v;
        float s0 = bn2g[j0] * rsqrtf(v0 + BN_EPS);
        float s1 = bn2g[j1] * rsqrtf(v1 + BN_EPS);
        sc2h[tid] = __floats2half2_rn(s0, s1);
        sh2h[tid] = __floats2half2_rn(bn2b[j0] - s0 * m0v, bn2b[j1] - s1 * m1v);
    }
    b3s[tid] = b3[tid];
    __syncthreads();

    // A-transform ONCE for both ck tiles (h2 read once per row-tile, was twice)
    #pragma unroll
    for (int ck = 0; ck < 2; ck++) {
        __half* Asd = ck ? As1 : As0;
        #pragma unroll
        for (int i = 0; i < 8; i++) {
            int idx = tid + i * 256;
            int r = idx >> 4, t = idx & 15;
            int grow = row0 + r;
            uint4 hv = make_uint4(0u, 0u, 0u, 0u);
            if (grow < Bc) {
                hv = *(const uint4*)(g_h2h + (size_t)grow * 256 + ck * 128 + t * 8);
                __half2* hp = (__half2*)&hv;
                int f2 = ck * 64 + t * 4;
                #pragma unroll
                for (int p = 0; p < 4; p++)
                    hp[p] = __hfma2_relu(hp[p], sc2h[f2 + p], sh2h[f2 + p]);
            }
            *(uint4*)(Asd + r * PAD + (t << 3)) = hv;
        }
    }
    CP_WAIT0();
    __syncthreads();

    int lane = tid & 31, wid = tid >> 5;
    int wr = wid >> 2, wc = wid & 3;
    int m0 = wr * 64, n0 = wc * 32;
    int lrow = lane & 7, mat = lane >> 3;
    int rb = (mat & 1) * 8, kb = (mat >> 1) * 8;

    uint32_t aA0[4], aA1[4], bA[2];
    #pragma unroll
    for (int i = 0; i < 4; i++) {
        aA0[i] = smem_u32(As0 + (m0 + i * 16 + rb + lrow) * PAD + kb);
        aA1[i] = smem_u32(As1 + (m0 + i * 16 + rb + lrow) * PAD + kb);
    }
    #pragma unroll
    for (int j = 0; j < 2; j++)
        bA[j] = smem_u32(Bs + (n0 + j * 16 + rb + lrow) * PAD + kb);

    float acc[4][4][4];

    auto run_ml = [&](const uint32_t* aA) {
        uint32_t afr[2][4][4], bfr[2][4][2];
        #pragma unroll
        for (int i = 0; i < 4; i++)
            ldmx4(afr[0][i][0], afr[0][i][1], afr[0][i][2], afr[0][i][3], aA[i]);
        #pragma unroll
        for (int j2 = 0; j2 < 2; j2++)
            ldmx4(bfr[0][2*j2][0], bfr[0][2*j2+1][0], bfr[0][2*j2][1], bfr[0][2*j2+1][1], bA[j2]);
        #pragma unroll
        for (int s = 0; s < 8; s++) {
            int cur = s & 1, nxt = cur ^ 1;
            if (s < 7) {
                #pragma unroll
                for (int i = 0; i < 4; i++)
                    ldmx4(afr[nxt][i][0], afr[nxt][i][1], afr[nxt][i][2], afr[nxt][i][3],
                          aA[i] + (s + 1) * 32);
                #pragma unroll
                for (int j2 = 0; j2 < 2; j2++)
                    ldmx4(bfr[nxt][2*j2][0], bfr[nxt][2*j2+1][0], bfr[nxt][2*j2][1],
                          bfr[nxt][2*j2+1][1], bA[j2] + (s + 1) * 32);
            }
            #pragma unroll
            for (int i = 0; i < 4; i++)
                #pragma unroll
                for (int j = 0; j < 4; j++)
                    mma_f16(acc[i][j], afr[cur][i], bfr[cur][j]);
        }
    };

    auto load_B = [&](int bc, int ck) {
        #pragma unroll
        for (int i = 0; i < 8; i++) {
            int idx = tid + i * 256;
            int n = idx >> 4, t = idx & 15;
            cp_async16(smem_u32(Bs + n * PAD + t * 8),
                       g_w3h + (size_t)(bc * 128 + n) * 256 + ck * 128 + t * 8);
        }
        CP_COMMIT();
    };

    // epilogue for one bc half: stage through Bs region as float[64][136]
    auto epilogue = [&](int bc) {
        float* stagef = (float*)Bs;          // 64*136*4 = 34816 B = Bs size
        #pragma unroll
        for (int p = 0; p < 2; p++) {
            if (p) __syncthreads();
            if (wr == p) {
                #pragma unroll
                for (int i = 0; i < 4; i++) {
                    #pragma unroll
                    for (int half = 0; half < 2; half++) {
                        int rloc = i * 16 + (lane >> 2) + half * 8;   // 0..63
                        #pragma unroll
                        for (int j = 0; j < 4; j++) {
                            int cloc = n0 + j * 8 + (lane & 3) * 2;
                            float2 o;
                            o.x = tanh_fast(acc[i][j][half * 2 + 0] + b3s[bc * 128 + cloc]);
                            o.y = tanh_fast(acc[i][j][half * 2 + 1] + b3s[bc * 128 + cloc + 1]);
                            *(float2*)(stagef + rloc * 136 + cloc) = o;
                        }
                    }
                }
            }
            __syncthreads();
            #pragma unroll
            for (int i2 = 0; i2 < 8; i2++) {
                int idx = tid + i2 * 256;
                int r = idx >> 5, t = idx & 31;
                int grow = row0 + p * 64 + r;
                if (grow < Bc) {
                    float4 v = *(float4*)(stagef + r * 136 + t * 4);
                    *(float4*)(out + (size_t)grow * 256 + bc * 128 + t * 4) = v;
                }
            }
        }
    };

    // ---- bc = 0 ----
    #pragma unroll
    for (int i = 0; i < 4; i++)
        #pragma unroll
        for (int j = 0; j < 4; j++)
            #pragma unroll
            for (int p = 0; p < 4; p++) acc[i][j][p] = 0.f;
    run_ml(aA0);                 // B(0,0) already resident
    __syncthreads();
    load_B(0, 1); CP_WAIT0(); __syncthreads();
    run_ml(aA1);
    __syncthreads();             // Bs free for staging
    epilogue(0);
    __syncthreads();             // stage reads done before B overwrite

    // ---- bc = 1 ----
    load_B(1, 0); CP_WAIT0(); __syncthreads();
    #pragma unroll
    for (int i = 0; i < 4; i++)
        #pragma unroll
        for (int j = 0; j < 4; j++)
            #pragma unroll
            for (int p = 0; p < 4; p++) acc[i][j][p] = 0.f;
    run_ml(aA0);
    __syncthreads();
    load_B(1, 1); CP_WAIT0(); __syncthreads();
    run_ml(aA1);
    __syncthreads();
    epilogue(1);

    // re-zero k_sim stat partials for the NEXT execution
    if (blockIdx.x == 0 && tid < 160) g_stat1[tid] = 0.f;
}

// ---------------- launch ------------------------------------------------------
extern "C" void kernel_launch(void* const* d_in, const int* in_sizes, int n_in,
                              void* d_out, int out_size) {
    const float* x     = (const float*)d_in[0];
    const float* qp    = (const float*)d_in[1];
    const float* fc1_w = (const float*)d_in[2];
    // d_in[3] = fc1_b (cancels in bn1), d_in[7] = fc2_b (cancels in bn2)
    const float* bn1_g = (const float*)d_in[4];
    const float* bn1_b = (const float*)d_in[5];
    const float* fc2_w = (const float*)d_in[6];
    const float* bn2_g = (const float*)d_in[8];
    const float* bn2_b = (const float*)d_in[9];
    const float* fc3_w = (const float*)d_in[10];
    const float* fc3_b = (const float*)d_in[11];
    float* out = (float*)d_out;

    int Bc = in_sizes[0] / 4;
    if (Bc > BMAX) Bc = BMAX;
    float binv = 1.0f / (float)Bc;
    int ntiles = (Bc + 127) / 128;

    const int SMEM2 = 2 * 128 * PAD * (int)sizeof(__half);  // 69632 B
    const int SMEM3 = 3 * 128 * PAD * (int)sizeof(__half);  // 104448 B
    cudaFuncSetAttribute(k_fc2, cudaFuncAttributeMaxDynamicSharedMemorySize, SMEM2);
    cudaFuncSetAttribute(k_fc3, cudaFuncAttributeMaxDynamicSharedMemorySize, SMEM3);

    k_sim<<<(Bc + 127) / 128, 128>>>(x, qp, fc2_w, fc3_w, Bc);

    dim3 gfc2(ntiles, 2);
    k_fc2<<<gfc2, 256, SMEM2>>>(fc1_w, bn1_g, bn1_b, Bc, binv);
    k_fc3<<<ntiles, 256, SMEM3>>>(fc3_b, bn2_g, bn2_b, out, Bc, binv);
}

// round 16
// speedup vs baseline: 1.5103x; 1.5103x over previous
#include <cuda_runtime.h>
#include <cuda_fp16.h>
#include <math.h>
#include <stdint.h>

#define BMAX 65536
#define BN_EPS 1e-5f
#define PAD 136   // halves per tile row: 272B = 17*16B -> ldmatrix conflict-free

// ---------------- scratch (static device globals; zero-initialized at load) ---
static __device__ float  g_q[BMAX * 4];
static __device__ __half g_h2h[(size_t)BMAX * 256];    // 32 MB, L2-resident
static __device__ __half g_w2h[256 * 128];
static __device__ __half g_w3h[256 * 256];
static __device__ float g_stat1[8 * 20];    // k_sim sumz/sumzz partials (8-way spread)
                                            // zeroed at end of k_fc3 for next run
static __device__ float g_s2s[4 * 256];     // fc2 column-sum partials (4-way spread)
static __device__ float g_s2q[4 * 256];     // zeroed in k_sim (fc2 runs after)

// ---------------- PTX helpers --------------------------------------------------
__device__ __forceinline__ uint32_t smem_u32(const void* p) {
    uint32_t a;
    asm("{ .reg .u64 t; cvta.to.shared.u64 t, %1; cvt.u32.u64 %0, t; }" : "=r"(a) : "l"(p));
    return a;
}
__device__ __forceinline__ void ldmx4(uint32_t& d0, uint32_t& d1, uint32_t& d2, uint32_t& d3,
                                      uint32_t addr) {
    asm volatile("ldmatrix.sync.aligned.m8n8.x4.shared.b16 {%0,%1,%2,%3}, [%4];"
                 : "=r"(d0), "=r"(d1), "=r"(d2), "=r"(d3) : "r"(addr));
}
__device__ __forceinline__ void mma_f16(float* c, const uint32_t* a, const uint32_t* b) {
    asm volatile(
        "mma.sync.aligned.m16n8k16.row.col.f32.f16.f16.f32 "
        "{%0,%1,%2,%3}, {%4,%5,%6,%7}, {%8,%9}, {%0,%1,%2,%3};"
        : "+f"(c[0]), "+f"(c[1]), "+f"(c[2]), "+f"(c[3])
        : "r"(a[0]), "r"(a[1]), "r"(a[2]), "r"(a[3]), "r"(b[0]), "r"(b[1]));
}
__device__ __forceinline__ uint32_t pack_half2(float x, float y) {
    __half2 h = __floats2half2_rn(x, y);
    return *(uint32_t*)&h;
}
__device__ __forceinline__ float tanh_fast(float x) {
    float y;
    asm("tanh.approx.f32 %0, %1;" : "=f"(y) : "f"(x));
    return y;
}
__device__ __forceinline__ void cp_async16(uint32_t saddr, const void* gptr) {
    asm volatile("cp.async.cg.shared.global [%0], [%1], 16;" :: "r"(saddr), "l"(gptr));
}
#define CP_COMMIT() asm volatile("cp.async.commit_group;" ::: "memory")
#define CP_WAIT0()  asm volatile("cp.async.wait_group 0;" ::: "memory")

// ---------------- quantum simulator (4 sincos/thread) + stats + fused prep ----
__global__ void k_sim(const float* __restrict__ x, const float* __restrict__ qp,
                      const float* __restrict__ w2, const float* __restrict__ w3,
                      int Bc) {
    int t = blockIdx.x * blockDim.x + threadIdx.x;

    // fused prep: fp16 weight conversion + zero fc2-stage partials
    if (t < 32768) g_w2h[t] = __float2half_rn(w2[t]);
    if (t < 65536) g_w3h[t] = __float2half_rn(w3[t]);
    if (t < 1024) { g_s2s[t] = 0.f; g_s2q[t] = 0.f; }

    // thread-uniform precompute: param sincos + full RZ phase tables
    __shared__ float sqp[24], cqp[24];
    __shared__ float phT[3][16], phTi[3][16];
    if (threadIdx.x < 24) {
        float s, c;
        __sincosf(0.5f * qp[threadIdx.x], &s, &c);
        sqp[threadIdx.x] = s; cqp[threadIdx.x] = c;
    }
    __syncthreads();
    if (threadIdx.x < 48) {
        int d = threadIdx.x >> 4, idx = threadIdx.x & 15;
        float pr = 1.f, pi = 0.f;
        #pragma unroll
        for (int i = 0; i < 4; i++) {
            int m = 1 << (3 - i);
            float c = cqp[d * 8 + 4 + i];
            float s = (idx & m) ? sqp[d * 8 + 4 + i] : -sqp[d * 8 + 4 + i];
            float nr = pr * c - pi * s;
            float ni = pr * s + pi * c;
            pr = nr; pi = ni;
        }
        phT[d][idx] = pr; phTi[d][idx] = pi;
    }
    __syncthreads();

    float z[4] = {0.f, 0.f, 0.f, 0.f};
    if (t < Bc) {
        float sx[4], cx[4];
        #pragma unroll
        for (int i = 0; i < 4; i++) {
            float xi = x[t * 4 + i];
            __sincosf(0.5f * xi, &sx[i], &cx[i]);
        }

        float re[16], im[16];

        // layer 0: product state (real)
        {
            float sy[4], cy[4];
            #pragma unroll
            for (int i = 0; i < 4; i++) {
                float sq = sqp[i], cq = cqp[i];
                sy[i] = sx[i] * cq + cx[i] * sq;
                cy[i] = cx[i] * cq - sx[i] * sq;
            }
            float p01[4] = {cy[0]*cy[1], cy[0]*sy[1], sy[0]*cy[1], sy[0]*sy[1]};
            float p23[4] = {cy[2]*cy[3], cy[2]*sy[3], sy[2]*cy[3], sy[2]*sy[3]};
            float r[16];
            #pragma unroll
            for (int idx = 0; idx < 16; idx++)
                r[idx] = p01[idx >> 2] * p23[idx & 3];
            #pragma unroll
            for (int i = 0; i < 4; i++) {
                int cm = 1 << (3 - i);
                int tm = 1 << (3 - ((i + 1) & 3));
                #pragma unroll
                for (int idx = 0; idx < 16; idx++) {
                    if ((idx & cm) && !(idx & tm)) {
                        int p = idx | tm;
                        float tr = r[idx]; r[idx] = r[p]; r[p] = tr;
                    }
                }
            }
            #pragma unroll
            for (int idx = 0; idx < 16; idx++) {
                re[idx] = r[idx] * phT[0][idx];
                im[idx] = r[idx] * phTi[0][idx];
            }
        }

        // layers 1,2
        #pragma unroll
        for (int d = 1; d < 3; d++) {
            #pragma unroll
            for (int i = 0; i < 4; i++) {
                float sq = sqp[d * 8 + i], cq = cqp[d * 8 + i];
                float s = sx[i] * cq + cx[i] * sq;
                float c = cx[i] * cq - sx[i] * sq;
                int m = 1 << (3 - i);
                #pragma unroll
                for (int idx = 0; idx < 16; idx++) {
                    if ((idx & m) == 0) {
                        int p = idx | m;
                        float a0r = re[idx], a0i = im[idx];
                        float a1r = re[p],  a1i = im[p];
                        re[idx] = c * a0r - s * a1r;  im[idx] = c * a0i - s * a1i;
                        re[p]   = s * a0r + c * a1r;  im[p]   = s * a0i + c * a1i;
                    }
                }
            }
            #pragma unroll
            for (int i = 0; i < 4; i++) {
                int cm = 1 << (3 - i);
                int tm = 1 << (3 - ((i + 1) & 3));
                #pragma unroll
                for (int idx = 0; idx < 16; idx++) {
                    if ((idx & cm) && !(idx & tm)) {
                        int p = idx | tm;
                        float tr = re[idx]; re[idx] = re[p]; re[p] = tr;
                        float ti = im[idx]; im[idx] = im[p]; im[p] = ti;
                    }
                }
            }
            #pragma unroll
            for (int idx = 0; idx < 16; idx++) {
                float phr = phT[d][idx], phi = phTi[d][idx];
                float r0 = re[idx], i0 = im[idx];
                re[idx] = r0 * phr - i0 * phi;
                im[idx] = r0 * phi + i0 * phr;
            }
        }

        float pr[16];
        #pragma unroll
        for (int idx = 0; idx < 16; idx++)
            pr[idx] = re[idx] * re[idx] + im[idx] * im[idx];
        #pragma unroll
        for (int i = 0; i < 4; i++) {
            int m = 1 << (3 - i);
            float acc = 0.f;
            #pragma unroll
            for (int idx = 0; idx < 16; idx++)
                acc += (idx & m) ? -pr[idx] : pr[idx];
            z[i] = acc;
        }
        *(float4*)(g_q + (size_t)t * 4) = make_float4(z[0], z[1], z[2], z[3]);
    }

    // stats: warp shuffle -> block smem reduce -> spread atomics
    __shared__ float wred[4][20];
    float vals[20];
    #pragma unroll
    for (int a = 0; a < 4; a++) vals[a] = z[a];
    #pragma unroll
    for (int a = 0; a < 4; a++)
        #pragma unroll
        for (int b = 0; b < 4; b++) vals[4 + a * 4 + b] = z[a] * z[b];
    #pragma unroll
    for (int v = 0; v < 20; v++) {
        #pragma unroll
        for (int off = 16; off > 0; off >>= 1)
            vals[v] += __shfl_xor_sync(0xffffffffu, vals[v], off);
    }
    int lane = threadIdx.x & 31, warp = threadIdx.x >> 5;
    if (lane == 0) {
        #pragma unroll
        for (int v = 0; v < 20; v++) wred[warp][v] = vals[v];
    }
    __syncthreads();
    if (threadIdx.x < 20) {
        float s = wred[0][threadIdx.x] + wred[1][threadIdx.x]
                + wred[2][threadIdx.x] + wred[3][threadIdx.x];
        atomicAdd(&g_stat1[(blockIdx.x & 7) * 20 + threadIdx.x], s);
    }
}

// ---------------- fc2: fp16 mma, cp.async B, fused bn1 + bn2 stats ------------
__global__ void __launch_bounds__(256, 2)
k_fc2(const float* __restrict__ w1,
      const float* __restrict__ bn1g, const float* __restrict__ bn1b,
      int Bc, float binv) {
    extern __shared__ char dynsm[];
    __half* As = (__half*)dynsm;             // [128][PAD]
    __half* Bs = As + 128 * PAD;             // [128][PAD]
    __shared__ float qs[512], w1s[512], sc1s[128], sh1s[128];
    __shared__ float redS[8 * 32], redQ[8 * 32];
    __shared__ float st1[20];

    int tid = threadIdx.x;
    int row0 = blockIdx.x * 128;
    int bc = blockIdx.y;

    #pragma unroll
    for (int i = 0; i < 8; i++) {
        int idx = tid + i * 256;
        int n = idx >> 4, t = idx & 15;
        cp_async16(smem_u32(Bs + n * PAD + t * 8),
                   g_w2h + (size_t)(bc * 128 + n) * 128 + t * 8);
    }
    CP_COMMIT();

    if (tid < 20) {
        float s = 0.f;
        #pragma unroll
        for (int p = 0; p < 8; p++) s += g_stat1[p * 20 + tid];
        st1[tid] = s;
    }
    w1s[tid] = w1[tid];
    w1s[tid + 256] = w1[tid + 256];
    if (tid < 128) {
        int r = row0 + tid;
        float4 q = (r < Bc) ? *(const float4*)(g_q + (size_t)r * 4)
                            : make_float4(0.f, 0.f, 0.f, 0.f);
        *(float4*)(qs + tid * 4) = q;
    }
    __syncthreads();

    if (tid < 128) {
        int j = tid;
        float mu[4], C[16];
        #pragma unroll
        for (int a = 0; a < 4; a++) mu[a] = st1[a] * binv;
        #pragma unroll
        for (int a = 0; a < 4; a++)
            #pragma unroll
            for (int c = 0; c < 4; c++)
                C[a * 4 + c] = st1[4 + a * 4 + c] * binv - mu[a] * mu[c];
        float w[4];
        #pragma unroll
        for (int a = 0; a < 4; a++) w[a] = w1s[j * 4 + a];
        float m0v = 0.f, v = 0.f;
        #pragma unroll
        for (int a = 0; a < 4; a++) {
            m0v += w[a] * mu[a];
            #pragma unroll
            for (int c = 0; c < 4; c++) v += w[a] * w[c] * C[a * 4 + c];
        }
        float sc = bn1g[j] * rsqrtf(v + BN_EPS);
        sc1s[j] = sc;
        sh1s[j] = bn1b[j] - sc * m0v;
    }
    __syncthreads();

    #pragma unroll
    for (int i = 0; i < 8; i++) {
        int idx = tid + i * 256;
        int r = idx >> 4, g8 = (idx & 15) << 3;
        bool valid = (row0 + r < Bc);
        float4 qv = *(const float4*)(qs + r * 4);
        uint32_t pk[4];
        #pragma unroll
        for (int p = 0; p < 4; p++) {
            int f0 = g8 + 2 * p, f1 = f0 + 1;
            float d0 = qv.x * w1s[f0 * 4] + qv.y * w1s[f0 * 4 + 1]
                     + qv.z * w1s[f0 * 4 + 2] + qv.w * w1s[f0 * 4 + 3];
            float d1 = qv.x * w1s[f1 * 4] + qv.y * w1s[f1 * 4 + 1]
                     + qv.z * w1s[f1 * 4 + 2] + qv.w * w1s[f1 * 4 + 3];
            float v0 = valid ? fmaxf(fmaf(sc1s[f0], d0, sh1s[f0]), 0.f) : 0.f;
            float v1 = valid ? fmaxf(fmaf(sc1s[f1], d1, sh1s[f1]), 0.f) : 0.f;
            pk[p] = pack_half2(v0, v1);
        }
        *(uint4*)(As + r * PAD + g8) = make_uint4(pk[0], pk[1], pk[2], pk[3]);
    }
    CP_WAIT0();
    __syncthreads();

    int lane = tid & 31, wid = tid >> 5;
    int wr = wid >> 2, wc = wid & 3;
    int m0 = wr * 64, n0 = wc * 32;
    int lrow = lane & 7, mat = lane >> 3;
    int rb = (mat & 1) * 8, kb = (mat >> 1) * 8;

    uint32_t aA[4], bA[2];
    #pragma unroll
    for (int i = 0; i < 4; i++)
        aA[i] = smem_u32(As + (m0 + i * 16 + rb + lrow) * PAD + kb);
    #pragma unroll
    for (int j = 0; j < 2; j++)
        bA[j] = smem_u32(Bs + (n0 + j * 16 + rb + lrow) * PAD + kb);

    float acc[4][4][4];
    #pragma unroll
    for (int i = 0; i < 4; i++)
        #pragma unroll
        for (int j = 0; j < 4; j++)
            #pragma unroll
            for (int p = 0; p < 4; p++) acc[i][j][p] = 0.f;

    uint32_t afr[2][4][4], bfr[2][4][2];
    {
        #pragma unroll
        for (int i = 0; i < 4; i++)
            ldmx4(afr[0][i][0], afr[0][i][1], afr[0][i][2], afr[0][i][3], aA[i]);
        #pragma unroll
        for (int j2 = 0; j2 < 2; j2++)
            ldmx4(bfr[0][2*j2][0], bfr[0][2*j2+1][0], bfr[0][2*j2][1], bfr[0][2*j2+1][1], bA[j2]);
    }
    #pragma unroll
    for (int s = 0; s < 8; s++) {
        int cur = s & 1, nxt = cur ^ 1;
        if (s < 7) {
            #pragma unroll
            for (int i = 0; i < 4; i++)
                ldmx4(afr[nxt][i][0], afr[nxt][i][1], afr[nxt][i][2], afr[nxt][i][3],
                      aA[i] + (s + 1) * 32);
            #pragma unroll
            for (int j2 = 0; j2 < 2; j2++)
                ldmx4(bfr[nxt][2*j2][0], bfr[nxt][2*j2+1][0], bfr[nxt][2*j2][1],
                      bfr[nxt][2*j2+1][1], bA[j2] + (s + 1) * 32);
        }
        #pragma unroll
        for (int i = 0; i < 4; i++)
            #pragma unroll
            for (int j = 0; j < 4; j++)
                mma_f16(acc[i][j], afr[cur][i], bfr[cur][j]);
    }

    __syncthreads();
    __half* stage = As;
    float cs[4][2], cq[4][2];
    #pragma unroll
    for (int j = 0; j < 4; j++) { cs[j][0] = cs[j][1] = cq[j][0] = cq[j][1] = 0.f; }

    #pragma unroll
    for (int i = 0; i < 4; i++) {
        #pragma unroll
        for (int half = 0; half < 2; half++) {
            int rloc = m0 + i * 16 + (lane >> 2) + half * 8;
            #pragma unroll
            for (int j = 0; j < 4; j++) {
                float v0 = acc[i][j][half * 2 + 0];
                float v1 = acc[i][j][half * 2 + 1];
                int cloc = n0 + j * 8 + (lane & 3) * 2;
                *(uint32_t*)(stage + rloc * PAD + cloc) = pack_half2(v0, v1);
                cs[j][0] += v0; cs[j][1] += v1;
                cq[j][0] += v0 * v0; cq[j][1] += v1 * v1;
            }
        }
    }
    #pragma unroll
    for (int j = 0; j < 4; j++)
        #pragma unroll
        for (int p = 0; p < 2; p++) {
            #pragma unroll
            for (int off = 4; off < 32; off <<= 1) {
                cs[j][p] += __shfl_xor_sync(0xffffffffu, cs[j][p], off);
                cq[j][p] += __shfl_xor_sync(0xffffffffu, cq[j][p], off);
            }
        }
    if (lane < 4) {
        #pragma unroll
        for (int j = 0; j < 4; j++)
            #pragma unroll
            for (int p = 0; p < 2; p++) {
                int c32 = j * 8 + lane * 2 + p;
                redS[wid * 32 + c32] = cs[j][p];
                redQ[wid * 32 + c32] = cq[j][p];
            }
    }
    __syncthreads();

    #pragma unroll
    for (int i = 0; i < 8; i++) {
        int idx = tid + i * 256;
        int r = idx >> 4, t = idx & 15;
        if (row0 + r < Bc) {
            uint4 v = *(uint4*)(stage + r * PAD + t * 8);
            *(uint4*)(g_h2h + (size_t)(row0 + r) * 256 + bc * 128 + t * 8) = v;
        }
    }
    if (tid < 128) {
        int wcq = tid >> 5, c32 = tid & 31;
        float s = redS[wcq * 32 + c32] + redS[(4 + wcq) * 32 + c32];
        float q = redQ[wcq * 32 + c32] + redQ[(4 + wcq) * 32 + c32];
        int slot = (blockIdx.x & 3) * 256 + bc * 128 + tid;
        atomicAdd(&g_s2s[slot], s);
        atomicAdd(&g_s2q[slot], q);
    }
}

// ---------------- fc3: fp16 mma (K=256), hfma2_relu bn2, tanh.approx out ------
__global__ void __launch_bounds__(256, 2)
k_fc3(const float* __restrict__ b3,
      const float* __restrict__ bn2g, const float* __restrict__ bn2b,
      float* __restrict__ out, int Bc, float binv) {
    extern __shared__ char dynsm[];
    __half* As = (__half*)dynsm;
    __half* Bs = As + 128 * PAD;
    __shared__ __half2 sc2h[128], sh2h[128];
    __shared__ float b3s[128];

    int tid = threadIdx.x;
    int row0 = blockIdx.x * 128;
    int bc = blockIdx.y;

    if (tid < 128) {   // bn2 params for col pair (2*tid, 2*tid+1), packed half2
        int j0 = 2 * tid, j1 = 2 * tid + 1;
        float s0g = 0.f, s1g = 0.f, q0g = 0.f, q1g = 0.f;
        #pragma unroll
        for (int p = 0; p < 4; p++) {
            s0g += g_s2s[p * 256 + j0];  s1g += g_s2s[p * 256 + j1];
            q0g += g_s2q[p * 256 + j0];  q1g += g_s2q[p * 256 + j1];
        }
        float m0v = s0g * binv, m1v = s1g * binv;
        float v0 = q0g * binv - m0v * m0v;
        float v1 = q1g * binv - m1v * m1v;
        float s0 = bn2g[j0] * rsqrtf(v0 + BN_EPS);
        float s1 = bn2g[j1] * rsqrtf(v1 + BN_EPS);
        sc2h[tid] = __floats2half2_rn(s0, s1);
        sh2h[tid] = __floats2half2_rn(bn2b[j0] - s0 * m0v, bn2b[j1] - s1 * m1v);
        b3s[tid] = b3[bc * 128 + tid];
    }

    int lane = tid & 31, wid = tid >> 5;
    int wr = wid >> 2, wc = wid & 3;
    int m0 = wr * 64, n0 = wc * 32;
    int lrow = lane & 7, mat = lane >> 3;
    int rb = (mat & 1) * 8, kb = (mat >> 1) * 8;

    uint32_t aA[4], bA[2];
    #pragma unroll
    for (int i = 0; i < 4; i++)
        aA[i] = smem_u32(As + (m0 + i * 16 + rb + lrow) * PAD + kb);
    #pragma unroll
    for (int j = 0; j < 2; j++)
        bA[j] = smem_u32(Bs + (n0 + j * 16 + rb + lrow) * PAD + kb);

    float acc[4][4][4];
    #pragma unroll
    for (int i = 0; i < 4; i++)
        #pragma unroll
        for (int j = 0; j < 4; j++)
            #pragma unroll
            for (int p = 0; p < 4; p++) acc[i][j][p] = 0.f;

    for (int ck = 0; ck < 2; ck++) {
        __syncthreads();   // ck=0: params staged; ck>0: tiles free
        #pragma unroll
        for (int i = 0; i < 8; i++) {
            int idx = tid + i * 256;
            int n = idx >> 4, t = idx & 15;
            cp_async16(smem_u32(Bs + n * PAD + t * 8),
                       g_w3h + (size_t)(bc * 128 + n) * 256 + ck * 128 + t * 8);
        }
        CP_COMMIT();
        #pragma unroll
        for (int i = 0; i < 8; i++) {
            int idx = tid + i * 256;
            int r = idx >> 4, t = idx & 15;
            int grow = row0 + r;
            uint4 hv = make_uint4(0u, 0u, 0u, 0u);
            if (grow < Bc) {
                hv = *(const uint4*)(g_h2h + (size_t)grow * 256 + ck * 128 + t * 8);
                __half2* hp = (__half2*)&hv;
                int f2 = ck * 64 + t * 4;
                #pragma unroll
                for (int p = 0; p < 4; p++)
                    hp[p] = __hfma2_relu(hp[p], sc2h[f2 + p], sh2h[f2 + p]);
            }
            *(uint4*)(As + r * PAD + (t << 3)) = hv;
        }
        CP_WAIT0();
        __syncthreads();

        uint32_t afr[2][4][4], bfr[2][4][2];
        {
            #pragma unroll
            for (int i = 0; i < 4; i++)
                ldmx4(afr[0][i][0], afr[0][i][1], afr[0][i][2], afr[0][i][3], aA[i]);
            #pragma unroll
            for (int j2 = 0; j2 < 2; j2++)
                ldmx4(bfr[0][2*j2][0], bfr[0][2*j2+1][0], bfr[0][2*j2][1], bfr[0][2*j2+1][1], bA[j2]);
        }
        #pragma unroll
        for (int s = 0; s < 8; s++) {
            int cur = s & 1, nxt = cur ^ 1;
            if (s < 7) {
                #pragma unroll
                for (int i = 0; i < 4; i++)
                    ldmx4(afr[nxt][i][0], afr[nxt][i][1], afr[nxt][i][2], afr[nxt][i][3],
                          aA[i] + (s + 1) * 32);
                #pragma unroll
                for (int j2 = 0; j2 < 2; j2++)
                    ldmx4(bfr[nxt][2*j2][0], bfr[nxt][2*j2+1][0], bfr[nxt][2*j2][1],
                          bfr[nxt][2*j2+1][1], bA[j2] + (s + 1) * 32);
            }
            #pragma unroll
            for (int i = 0; i < 4; i++)
                #pragma unroll
                for (int j = 0; j < 4; j++)
                    mma_f16(acc[i][j], afr[cur][i], bfr[cur][j]);
        }
    }

    // epilogue: +bias, tanh.approx, fp32 staging -> coalesced stores
    __syncthreads();
    float* stagef = (float*)dynsm;            // [128][136] f32 = 69632 B exactly
    #pragma unroll
    for (int i = 0; i < 4; i++) {
        #pragma unroll
        for (int half = 0; half < 2; half++) {
            int rloc = m0 + i * 16 + (lane >> 2) + half * 8;
            #pragma unroll
            for (int j = 0; j < 4; j++) {
                int cloc = n0 + j * 8 + (lane & 3) * 2;
                float2 o;
                o.x = tanh_fast(acc[i][j][half * 2 + 0] + b3s[cloc]);
                o.y = tanh_fast(acc[i][j][half * 2 + 1] + b3s[cloc + 1]);
                *(float2*)(stagef + rloc * 136 + cloc) = o;
            }
        }
    }
    __syncthreads();
    #pragma unroll
    for (int i = 0; i < 16; i++) {
        int idx = tid + i * 256;
        int r = idx >> 5, t = idx & 31;
        if (row0 + r < Bc) {
            float4 v = *(float4*)(stagef + r * 136 + t * 4);
            *(float4*)(out + (size_t)(row0 + r) * 256 + bc * 128 + t * 4) = v;
        }
    }

    // re-zero k_sim stat partials for the NEXT execution (all fc2 consumers done;
    // statics are zero-initialized at load so the first run is also correct)
    if (blockIdx.x == 0 && blockIdx.y == 0 && tid < 160) g_stat1[tid] = 0.f;
}

// ---------------- launch ------------------------------------------------------
extern "C" void kernel_launch(void* const* d_in, const int* in_sizes, int n_in,
                              void* d_out, int out_size) {
    const float* x     = (const float*)d_in[0];
    const float* qp    = (const float*)d_in[1];
    const float* fc1_w = (const float*)d_in[2];
    // d_in[3] = fc1_b (cancels in bn1), d_in[7] = fc2_b (cancels in bn2)
    const float* bn1_g = (const float*)d_in[4];
    const float* bn1_b = (const float*)d_in[5];
    const float* fc2_w = (const float*)d_in[6];
    const float* bn2_g = (const float*)d_in[8];
    const float* bn2_b = (const float*)d_in[9];
    const float* fc3_w = (const float*)d_in[10];
    const float* fc3_b = (const float*)d_in[11];
    float* out = (float*)d_out;

    int Bc = in_sizes[0] / 4;
    if (Bc > BMAX) Bc = BMAX;
    float binv = 1.0f / (float)Bc;

    const int SMEM = 2 * 128 * PAD * (int)sizeof(__half);  // 69632 B
    cudaFuncSetAttribute(k_fc2, cudaFuncAttributeMaxDynamicSharedMemorySize, SMEM);
    cudaFuncSetAttribute(k_fc3, cudaFuncAttributeMaxDynamicSharedMemorySize, SMEM);

    k_sim<<<(Bc + 127) / 128, 128>>>(x, qp, fc2_w, fc3_w, Bc);

    dim3 gfc((Bc + 127) / 128, 2);
    k_fc2<<<gfc, 256, SMEM>>>(fc1_w, bn1_g, bn1_b, Bc, binv);
    k_fc3<<<gfc, 256, SMEM>>>(fc3_b, bn2_g, bn2_b, out, Bc, binv);
}

// round 17
// speedup vs baseline: 1.5956x; 1.0565x over previous
#include <cuda_runtime.h>
#include <cuda_fp16.h>
#include <math.h>
#include <stdint.h>

#define BMAX 65536
#define BN_EPS 1e-5f
#define PAD 136   // halves per tile row: 272B = 17*16B -> ldmatrix conflict-free

// ---------------- scratch (static device globals; zero-initialized at load) ---
static __device__ float  g_q[BMAX * 4];
static __device__ __half g_h2h[(size_t)BMAX * 256];    // 32 MB, L2-resident
static __device__ __half g_w2h[256 * 128];
static __device__ __half g_w3h[256 * 256];
static __device__ float g_stat1[8 * 20];    // k_sim sumz/sumzz partials (8-way spread)
                                            // zeroed at end of k_fc3 for next run
static __device__ float g_s2s[4 * 256];     // fc2 column-sum partials (4-way spread)
static __device__ float g_s2q[4 * 256];     // zeroed in k_sim (fc2 runs after)

// ---------------- PTX helpers --------------------------------------------------
__device__ __forceinline__ uint32_t smem_u32(const void* p) {
    uint32_t a;
    asm("{ .reg .u64 t; cvta.to.shared.u64 t, %1; cvt.u32.u64 %0, t; }" : "=r"(a) : "l"(p));
    return a;
}
__device__ __forceinline__ void ldmx4(uint32_t& d0, uint32_t& d1, uint32_t& d2, uint32_t& d3,
                                      uint32_t addr) {
    asm volatile("ldmatrix.sync.aligned.m8n8.x4.shared.b16 {%0,%1,%2,%3}, [%4];"
                 : "=r"(d0), "=r"(d1), "=r"(d2), "=r"(d3) : "r"(addr));
}
__device__ __forceinline__ void mma_f16(float* c, const uint32_t* a, const uint32_t* b) {
    asm volatile(
        "mma.sync.aligned.m16n8k16.row.col.f32.f16.f16.f32 "
        "{%0,%1,%2,%3}, {%4,%5,%6,%7}, {%8,%9}, {%0,%1,%2,%3};"
        : "+f"(c[0]), "+f"(c[1]), "+f"(c[2]), "+f"(c[3])
        : "r"(a[0]), "r"(a[1]), "r"(a[2]), "r"(a[3]), "r"(b[0]), "r"(b[1]));
}
__device__ __forceinline__ uint32_t pack_half2(float x, float y) {
    __half2 h = __floats2half2_rn(x, y);
    return *(uint32_t*)&h;
}
__device__ __forceinline__ float tanh_fast(float x) {
    float y;
    asm("tanh.approx.f32 %0, %1;" : "=f"(y) : "f"(x));
    return y;
}
__device__ __forceinline__ void cp_async16(uint32_t saddr, const void* gptr) {
    asm volatile("cp.async.ca.shared.global [%0], [%1], 16;" :: "r"(saddr), "l"(gptr));
}
__device__ __forceinline__ void st_cs128(float* gptr, float4 v) {
    asm volatile("st.global.cs.v4.f32 [%0], {%1,%2,%3,%4};"
                 :: "l"(gptr), "f"(v.x), "f"(v.y), "f"(v.z), "f"(v.w) : "memory");
}
#define CP_COMMIT() asm volatile("cp.async.commit_group;" ::: "memory")
#define CP_WAIT0()  asm volatile("cp.async.wait_group 0;" ::: "memory")

// ---------------- quantum simulator (4 sincos/thread) + stats + fused prep ----
__global__ void k_sim(const float* __restrict__ x, const float* __restrict__ qp,
                      const float* __restrict__ w2, const float* __restrict__ w3,
                      int Bc) {
    int t = blockIdx.x * blockDim.x + threadIdx.x;

    // fused prep: fp16 weight conversion + zero fc2-stage partials
    if (t < 32768) g_w2h[t] = __float2half_rn(w2[t]);
    if (t < 65536) g_w3h[t] = __float2half_rn(w3[t]);
    if (t < 1024) { g_s2s[t] = 0.f; g_s2q[t] = 0.f; }

    // thread-uniform precompute: param sincos + full RZ phase tables
    __shared__ float sqp[24], cqp[24];
    __shared__ float phT[3][16], phTi[3][16];
    if (threadIdx.x < 24) {
        float s, c;
        __sincosf(0.5f * qp[threadIdx.x], &s, &c);
        sqp[threadIdx.x] = s; cqp[threadIdx.x] = c;
    }
    __syncthreads();
    if (threadIdx.x < 48) {
        int d = threadIdx.x >> 4, idx = threadIdx.x & 15;
        float pr = 1.f, pi = 0.f;
        #pragma unroll
        for (int i = 0; i < 4; i++) {
            int m = 1 << (3 - i);
            float c = cqp[d * 8 + 4 + i];
            float s = (idx & m) ? sqp[d * 8 + 4 + i] : -sqp[d * 8 + 4 + i];
            float nr = pr * c - pi * s;
            float ni = pr * s + pi * c;
            pr = nr; pi = ni;
        }
        phT[d][idx] = pr; phTi[d][idx] = pi;
    }
    __syncthreads();

    float z[4] = {0.f, 0.f, 0.f, 0.f};
    if (t < Bc) {
        float sx[4], cx[4];
        #pragma unroll
        for (int i = 0; i < 4; i++) {
            float xi = x[t * 4 + i];
            __sincosf(0.5f * xi, &sx[i], &cx[i]);
        }

        float re[16], im[16];

        // layer 0: product state (real)
        {
            float sy[4], cy[4];
            #pragma unroll
            for (int i = 0; i < 4; i++) {
                float sq = sqp[i], cq = cqp[i];
                sy[i] = sx[i] * cq + cx[i] * sq;
                cy[i] = cx[i] * cq - sx[i] * sq;
            }
            float p01[4] = {cy[0]*cy[1], cy[0]*sy[1], sy[0]*cy[1], sy[0]*sy[1]};
            float p23[4] = {cy[2]*cy[3], cy[2]*sy[3], sy[2]*cy[3], sy[2]*sy[3]};
            float r[16];
            #pragma unroll
            for (int idx = 0; idx < 16; idx++)
                r[idx] = p01[idx >> 2] * p23[idx & 3];
            #pragma unroll
            for (int i = 0; i < 4; i++) {
                int cm = 1 << (3 - i);
                int tm = 1 << (3 - ((i + 1) & 3));
                #pragma unroll
                for (int idx = 0; idx < 16; idx++) {
                    if ((idx & cm) && !(idx & tm)) {
                        int p = idx | tm;
                        float tr = r[idx]; r[idx] = r[p]; r[p] = tr;
                    }
                }
            }
            #pragma unroll
            for (int idx = 0; idx < 16; idx++) {
                re[idx] = r[idx] * phT[0][idx];
                im[idx] = r[idx] * phTi[0][idx];
            }
        }

        // layers 1,2
        #pragma unroll
        for (int d = 1; d < 3; d++) {
            #pragma unroll
            for (int i = 0; i < 4; i++) {
                float sq = sqp[d * 8 + i], cq = cqp[d * 8 + i];
                float s = sx[i] * cq + cx[i] * sq;
                float c = cx[i] * cq - sx[i] * sq;
                int m = 1 << (3 - i);
                #pragma unroll
                for (int idx = 0; idx < 16; idx++) {
                    if ((idx & m) == 0) {
                        int p = idx | m;
                        float a0r = re[idx], a0i = im[idx];
                        float a1r = re[p],  a1i = im[p];
                        re[idx] = c * a0r - s * a1r;  im[idx] = c * a0i - s * a1i;
                        re[p]   = s * a0r + c * a1r;  im[p]   = s * a0i + c * a1i;
                    }
                }
            }
            #pragma unroll
            for (int i = 0; i < 4; i++) {
                int cm = 1 << (3 - i);
                int tm = 1 << (3 - ((i + 1) & 3));
                #pragma unroll
                for (int idx = 0; idx < 16; idx++) {
                    if ((idx & cm) && !(idx & tm)) {
                        int p = idx | tm;
                        float tr = re[idx]; re[idx] = re[p]; re[p] = tr;
                        float ti = im[idx]; im[idx] = im[p]; im[p] = ti;
                    }
                }
            }
            #pragma unroll
            for (int idx = 0; idx < 16; idx++) {
                float phr = phT[d][idx], phi = phTi[d][idx];
                float r0 = re[idx], i0 = im[idx];
                re[idx] = r0 * phr - i0 * phi;
                im[idx] = r0 * phi + i0 * phr;
            }
        }

        float pr[16];
        #pragma unroll
        for (int idx = 0; idx < 16; idx++)
            pr[idx] = re[idx] * re[idx] + im[idx] * im[idx];
        #pragma unroll
        for (int i = 0; i < 4; i++) {
            int m = 1 << (3 - i);
            float acc = 0.f;
            #pragma unroll
            for (int idx = 0; idx < 16; idx++)
                acc += (idx & m) ? -pr[idx] : pr[idx];
            z[i] = acc;
        }
        *(float4*)(g_q + (size_t)t * 4) = make_float4(z[0], z[1], z[2], z[3]);
    }

    // stats: warp shuffle -> block smem reduce -> spread atomics
    __shared__ float wred[4][20];
    float vals[20];
    #pragma unroll
    for (int a = 0; a < 4; a++) vals[a] = z[a];
    #pragma unroll
    for (int a = 0; a < 4; a++)
        #pragma unroll
        for (int b = 0; b < 4; b++) vals[4 + a * 4 + b] = z[a] * z[b];
    #pragma unroll
    for (int v = 0; v < 20; v++) {
        #pragma unroll
        for (int off = 16; off > 0; off >>= 1)
            vals[v] += __shfl_xor_sync(0xffffffffu, vals[v], off);
    }
    int lane = threadIdx.x & 31, warp = threadIdx.x >> 5;
    if (lane == 0) {
        #pragma unroll
        for (int v = 0; v < 20; v++) wred[warp][v] = vals[v];
    }
    __syncthreads();
    if (threadIdx.x < 20) {
        float s = wred[0][threadIdx.x] + wred[1][threadIdx.x]
                + wred[2][threadIdx.x] + wred[3][threadIdx.x];
        atomicAdd(&g_stat1[(blockIdx.x & 7) * 20 + threadIdx.x], s);
    }
}

// ---------------- fc2: fp16 mma, cp.async B, fused bn1 + bn2 stats ------------
__global__ void __launch_bounds__(256, 2)
k_fc2(const float* __restrict__ w1,
      const float* __restrict__ bn1g, const float* __restrict__ bn1b,
      int Bc, float binv) {
    extern __shared__ char dynsm[];
    __half* As = (__half*)dynsm;             // [128][PAD]
    __half* Bs = As + 128 * PAD;             // [128][PAD]
    __shared__ float qs[512], w1s[512], sc1s[128], sh1s[128];
    __shared__ float redS[8 * 32], redQ[8 * 32];
    __shared__ float st1[20];

    int tid = threadIdx.x;
    int row0 = blockIdx.x * 128;
    int bc = blockIdx.y;

    #pragma unroll
    for (int i = 0; i < 8; i++) {
        int idx = tid + i * 256;
        int n = idx >> 4, t = idx & 15;
        cp_async16(smem_u32(Bs + n * PAD + t * 8),
                   g_w2h + (size_t)(bc * 128 + n) * 128 + t * 8);
    }
    CP_COMMIT();

    if (tid < 20) {
        float s = 0.f;
        #pragma unroll
        for (int p = 0; p < 8; p++) s += g_stat1[p * 20 + tid];
        st1[tid] = s;
    }
    w1s[tid] = w1[tid];
    w1s[tid + 256] = w1[tid + 256];
    if (tid < 128) {
        int r = row0 + tid;
        float4 q = (r < Bc) ? *(const float4*)(g_q + (size_t)r * 4)
                            : make_float4(0.f, 0.f, 0.f, 0.f);
        *(float4*)(qs + tid * 4) = q;
    }
    __syncthreads();

    if (tid < 128) {
        int j = tid;
        float mu[4], C[16];
        #pragma unroll
        for (int a = 0; a < 4; a++) mu[a] = st1[a] * binv;
        #pragma unroll
        for (int a = 0; a < 4; a++)
            #pragma unroll
            for (int c = 0; c < 4; c++)
                C[a * 4 + c] = st1[4 + a * 4 + c] * binv - mu[a] * mu[c];
        float w[4];
        #pragma unroll
        for (int a = 0; a < 4; a++) w[a] = w1s[j * 4 + a];
        float m0v = 0.f, v = 0.f;
        #pragma unroll
        for (int a = 0; a < 4; a++) {
            m0v += w[a] * mu[a];
            #pragma unroll
            for (int c = 0; c < 4; c++) v += w[a] * w[c] * C[a * 4 + c];
        }
        float sc = bn1g[j] * rsqrtf(v + BN_EPS);
        sc1s[j] = sc;
        sh1s[j] = bn1b[j] - sc * m0v;
    }
    __syncthreads();

    #pragma unroll
    for (int i = 0; i < 8; i++) {
        int idx = tid + i * 256;
        int r = idx >> 4, g8 = (idx & 15) << 3;
        bool valid = (row0 + r < Bc);
        float4 qv = *(const float4*)(qs + r * 4);
        uint32_t pk[4];
        #pragma unroll
        for (int p = 0; p < 4; p++) {
            int f0 = g8 + 2 * p, f1 = f0 + 1;
            float d0 = qv.x * w1s[f0 * 4] + qv.y * w1s[f0 * 4 + 1]
                     + qv.z * w1s[f0 * 4 + 2] + qv.w * w1s[f0 * 4 + 3];
            float d1 = qv.x * w1s[f1 * 4] + qv.y * w1s[f1 * 4 + 1]
                     + qv.z * w1s[f1 * 4 + 2] + qv.w * w1s[f1 * 4 + 3];
            float v0 = valid ? fmaxf(fmaf(sc1s[f0], d0, sh1s[f0]), 0.f) : 0.f;
            float v1 = valid ? fmaxf(fmaf(sc1s[f1], d1, sh1s[f1]), 0.f) : 0.f;
            pk[p] = pack_half2(v0, v1);
        }
        *(uint4*)(As + r * PAD + g8) = make_uint4(pk[0], pk[1], pk[2], pk[3]);
    }
    CP_WAIT0();
    __syncthreads();

    int lane = tid & 31, wid = tid >> 5;
    int wr = wid >> 2, wc = wid & 3;
    int m0 = wr * 64, n0 = wc * 32;
    int lrow = lane & 7, mat = lane >> 3;
    int rb = (mat & 1) * 8, kb = (mat >> 1) * 8;

    uint32_t aA[4], bA[2];
    #pragma unroll
    for (int i = 0; i < 4; i++)
        aA[i] = smem_u32(As + (m0 + i * 16 + rb + lrow) * PAD + kb);
    #pragma unroll
    for (int j = 0; j < 2; j++)
        bA[j] = smem_u32(Bs + (n0 + j * 16 + rb + lrow) * PAD + kb);

    float acc[4][4][4];
    #pragma unroll
    for (int i = 0; i < 4; i++)
        #pragma unroll
        for (int j = 0; j < 4; j++)
            #pragma unroll
            for (int p = 0; p < 4; p++) acc[i][j][p] = 0.f;

    uint32_t afr[2][4][4], bfr[2][4][2];
    {
        #pragma unroll
        for (int i = 0; i < 4; i++)
            ldmx4(afr[0][i][0], afr[0][i][1], afr[0][i][2], afr[0][i][3], aA[i]);
        #pragma unroll
        for (int j2 = 0; j2 < 2; j2++)
            ldmx4(bfr[0][2*j2][0], bfr[0][2*j2+1][0], bfr[0][2*j2][1], bfr[0][2*j2+1][1], bA[j2]);
    }
    #pragma unroll
    for (int s = 0; s < 8; s++) {
        int cur = s & 1, nxt = cur ^ 1;
        if (s < 7) {
            #pragma unroll
            for (int i = 0; i < 4; i++)
                ldmx4(afr[nxt][i][0], afr[nxt][i][1], afr[nxt][i][2], afr[nxt][i][3],
                      aA[i] + (s + 1) * 32);
            #pragma unroll
            for (int j2 = 0; j2 < 2; j2++)
                ldmx4(bfr[nxt][2*j2][0], bfr[nxt][2*j2+1][0], bfr[nxt][2*j2][1],
                      bfr[nxt][2*j2+1][1], bA[j2] + (s + 1) * 32);
        }
        #pragma unroll
        for (int i = 0; i < 4; i++)
            #pragma unroll
            for (int j = 0; j < 4; j++)
                mma_f16(acc[i][j], afr[cur][i], bfr[cur][j]);
    }

    __syncthreads();
    __half* stage = As;
    float cs[4][2], cq[4][2];
    #pragma unroll
    for (int j = 0; j < 4; j++) { cs[j][0] = cs[j][1] = cq[j][0] = cq[j][1] = 0.f; }

    #pragma unroll
    for (int i = 0; i < 4; i++) {
        #pragma unroll
        for (int half = 0; half < 2; half++) {
            int rloc = m0 + i * 16 + (lane >> 2) + half * 8;
            #pragma unroll
            for (int j = 0; j < 4; j++) {
                float v0 = acc[i][j][half * 2 + 0];
                float v1 = acc[i][j][half * 2 + 1];
                int cloc = n0 + j * 8 + (lane & 3) * 2;
                *(uint32_t*)(stage + rloc * PAD + cloc) = pack_half2(v0, v1);
                cs[j][0] += v0; cs[j][1] += v1;
                cq[j][0] += v0 * v0; cq[j][1] += v1 * v1;
            }
        }
    }
    #pragma unroll
    for (int j = 0; j < 4; j++)
        #pragma unroll
        for (int p = 0; p < 2; p++) {
            #pragma unroll
            for (int off = 4; off < 32; off <<= 1) {
                cs[j][p] += __shfl_xor_sync(0xffffffffu, cs[j][p], off);
                cq[j][p] += __shfl_xor_sync(0xffffffffu, cq[j][p], off);
            }
        }
    if (lane < 4) {
        #pragma unroll
        for (int j = 0; j < 4; j++)
            #pragma unroll
            for (int p = 0; p < 2; p++) {
                int c32 = j * 8 + lane * 2 + p;
                redS[wid * 32 + c32] = cs[j][p];
                redQ[wid * 32 + c32] = cq[j][p];
            }
    }
    __syncthreads();

    #pragma unroll
    for (int i = 0; i < 8; i++) {
        int idx = tid + i * 256;
        int r = idx >> 4, t = idx & 15;
        if (row0 + r < Bc) {
            uint4 v = *(uint4*)(stage + r * PAD + t * 8);
            *(uint4*)(g_h2h + (size_t)(row0 + r) * 256 + bc * 128 + t * 8) = v;
        }
    }
    if (tid < 128) {
        int wcq = tid >> 5, c32 = tid & 31;
        float s = redS[wcq * 32 + c32] + redS[(4 + wcq) * 32 + c32];
        float q = redQ[wcq * 32 + c32] + redQ[(4 + wcq) * 32 + c32];
        int slot = (blockIdx.x & 3) * 256 + bc * 128 + tid;
        atomicAdd(&g_s2s[slot], s);
        atomicAdd(&g_s2q[slot], q);
    }
}

// ---------------- fc3: fp16 mma (K=256), hfma2_relu bn2, tanh.approx out ------
__global__ void __launch_bounds__(256, 2)
k_fc3(const float* __restrict__ b3,
      const float* __restrict__ bn2g, const float* __restrict__ bn2b,
      float* __restrict__ out, int Bc, float binv) {
    extern __shared__ char dynsm[];
    __half* As = (__half*)dynsm;
    __half* Bs = As + 128 * PAD;
    __shared__ __half2 sc2h[128], sh2h[128];
    __shared__ float b3s[128];

    int tid = threadIdx.x;
    int row0 = blockIdx.x * 128;
    int bc = blockIdx.y;

    if (tid < 128) {   // bn2 params for col pair (2*tid, 2*tid+1), packed half2
        int j0 = 2 * tid, j1 = 2 * tid + 1;
        float s0g = 0.f, s1g = 0.f, q0g = 0.f, q1g = 0.f;
        #pragma unroll
        for (int p = 0; p < 4; p++) {
            s0g += g_s2s[p * 256 + j0];  s1g += g_s2s[p * 256 + j1];
            q0g += g_s2q[p * 256 + j0];  q1g += g_s2q[p * 256 + j1];
        }
        float m0v = s0g * binv, m1v = s1g * binv;
        float v0 = q0g * binv - m0v * m0v;
        float v1 = q1g * binv - m1v * m1v;
        float s0 = bn2g[j0] * rsqrtf(v0 + BN_EPS);
        float s1 = bn2g[j1] * rsqrtf(v1 + BN_EPS);
        sc2h[tid] = __floats2half2_rn(s0, s1);
        sh2h[tid] = __floats2half2_rn(bn2b[j0] - s0 * m0v, bn2b[j1] - s1 * m1v);
        b3s[tid] = b3[bc * 128 + tid];
    }

    int lane = tid & 31, wid = tid >> 5;
    int wr = wid >> 2, wc = wid & 3;
    int m0 = wr * 64, n0 = wc * 32;
    int lrow = lane & 7, mat = lane >> 3;
    int rb = (mat & 1) * 8, kb = (mat >> 1) * 8;

    uint32_t aA[4], bA[2];
    #pragma unroll
    for (int i = 0; i < 4; i++)
        aA[i] = smem_u32(As + (m0 + i * 16 + rb + lrow) * PAD + kb);
    #pragma unroll
    for (int j = 0; j < 2; j++)
        bA[j] = smem_u32(Bs + (n0 + j * 16 + rb + lrow) * PAD + kb);

    float acc[4][4][4];
    #pragma unroll
    for (int i = 0; i < 4; i++)
        #pragma unroll
        for (int j = 0; j < 4; j++)
            #pragma unroll
            for (int p = 0; p < 4; p++) acc[i][j][p] = 0.f;

    for (int ck = 0; ck < 2; ck++) {
        __syncthreads();   // ck=0: params staged; ck>0: tiles free
        #pragma unroll
        for (int i = 0; i < 8; i++) {
            int idx = tid + i * 256;
            int n = idx >> 4, t = idx & 15;
            cp_async16(smem_u32(Bs + n * PAD + t * 8),
                       g_w3h + (size_t)(bc * 128 + n) * 256 + ck * 128 + t * 8);
        }
        CP_COMMIT();
        #pragma unroll
        for (int i = 0; i < 8; i++) {
            int idx = tid + i * 256;
            int r = idx >> 4, t = idx & 15;
            int grow = row0 + r;
            uint4 hv = make_uint4(0u, 0u, 0u, 0u);
            if (grow < Bc) {
                hv = *(const uint4*)(g_h2h + (size_t)grow * 256 + ck * 128 + t * 8);
                __half2* hp = (__half2*)&hv;
                int f2 = ck * 64 + t * 4;
                #pragma unroll
                for (int p = 0; p < 4; p++)
                    hp[p] = __hfma2_relu(hp[p], sc2h[f2 + p], sh2h[f2 + p]);
            }
            *(uint4*)(As + r * PAD + (t << 3)) = hv;
        }
        CP_WAIT0();
        __syncthreads();

        uint32_t afr[2][4][4], bfr[2][4][2];
        {
            #pragma unroll
            for (int i = 0; i < 4; i++)
                ldmx4(afr[0][i][0], afr[0][i][1], afr[0][i][2], afr[0][i][3], aA[i]);
            #pragma unroll
            for (int j2 = 0; j2 < 2; j2++)
                ldmx4(bfr[0][2*j2][0], bfr[0][2*j2+1][0], bfr[0][2*j2][1], bfr[0][2*j2+1][1], bA[j2]);
        }
        #pragma unroll
        for (int s = 0; s < 8; s++) {
            int cur = s & 1, nxt = cur ^ 1;
            if (s < 7) {
                #pragma unroll
                for (int i = 0; i < 4; i++)
                    ldmx4(afr[nxt][i][0], afr[nxt][i][1], afr[nxt][i][2], afr[nxt][i][3],
                          aA[i] + (s + 1) * 32);
                #pragma unroll
                for (int j2 = 0; j2 < 2; j2++)
                    ldmx4(bfr[nxt][2*j2][0], bfr[nxt][2*j2+1][0], bfr[nxt][2*j2][1],
                          bfr[nxt][2*j2+1][1], bA[j2] + (s + 1) * 32);
            }
            #pragma unroll
            for (int i = 0; i < 4; i++)
                #pragma unroll
                for (int j = 0; j < 4; j++)
                    mma_f16(acc[i][j], afr[cur][i], bfr[cur][j]);
        }
    }

    // epilogue: +bias, tanh.approx, fp32 staging -> coalesced streaming stores
    __syncthreads();
    float* stagef = (float*)dynsm;            // [128][136] f32 = 69632 B exactly
    #pragma unroll
    for (int i = 0; i < 4; i++) {
        #pragma unroll
        for (int half = 0; half < 2; half++) {
            int rloc = m0 + i * 16 + (lane >> 2) + half * 8;
            #pragma unroll
            for (int j = 0; j < 4; j++) {
                int cloc = n0 + j * 8 + (lane & 3) * 2;
                float2 o;
                o.x = tanh_fast(acc[i][j][half * 2 + 0] + b3s[cloc]);
                o.y = tanh_fast(acc[i][j][half * 2 + 1] + b3s[cloc + 1]);
                *(float2*)(stagef + rloc * 136 + cloc) = o;
            }
        }
    }
    __syncthreads();
    #pragma unroll
    for (int i = 0; i < 16; i++) {
        int idx = tid + i * 256;
        int r = idx >> 5, t = idx & 31;
        if (row0 + r < Bc) {
            float4 v = *(float4*)(stagef + r * 136 + t * 4);
            st_cs128(out + (size_t)(row0 + r) * 256 + bc * 128 + t * 4, v);
        }
    }

    // re-zero k_sim stat partials for the NEXT execution (all fc2 consumers done;
    // statics are zero-initialized at load so the first run is also correct)
    if (blockIdx.x == 0 && blockIdx.y == 0 && tid < 160) g_stat1[tid] = 0.f;
}

// ---------------- launch ------------------------------------------------------
extern "C" void kernel_launch(void* const* d_in, const int* in_sizes, int n_in,
                              void* d_out, int out_size) {
    const float* x     = (const float*)d_in[0];
    const float* qp    = (const float*)d_in[1];
    const float* fc1_w = (const float*)d_in[2];
    // d_in[3] = fc1_b (cancels in bn1), d_in[7] = fc2_b (cancels in bn2)
    const float* bn1_g = (const float*)d_in[4];
    const float* bn1_b = (const float*)d_in[5];
    const float* fc2_w = (const float*)d_in[6];
    const float* bn2_g = (const float*)d_in[8];
    const float* bn2_b = (const float*)d_in[9];
    const float* fc3_w = (const float*)d_in[10];
    const float* fc3_b = (const float*)d_in[11];
    float* out = (float*)d_out;

    int Bc = in_sizes[0] / 4;
    if (Bc > BMAX) Bc = BMAX;
    float binv = 1.0f / (float)Bc;

    const int SMEM = 2 * 128 * PAD * (int)sizeof(__half);  // 69632 B
    cudaFuncSetAttribute(k_fc2, cudaFuncAttributeMaxDynamicSharedMemorySize, SMEM);
    cudaFuncSetAttribute(k_fc3, cudaFuncAttributeMaxDynamicSharedMemorySize, SMEM);

    k_sim<<<(Bc + 127) / 128, 128>>>(x, qp, fc2_w, fc3_w, Bc);

    dim3 gfc((Bc + 127) / 128, 2);
    k_fc2<<<gfc, 256, SMEM>>>(fc1_w, bn1_g, bn1_b, Bc, binv);
    k_fc3<<<gfc, 256, SMEM>>>(fc3_b, bn2_g, bn2_b, out, Bc, binv);
}